// round 1
// baseline (speedup 1.0000x reference)
#include <cuda_runtime.h>

#define HDIM 2880
#define NEXP 32
#define TOPK 4
#define TOK_TILE 64
#define HC 120          // H-chunk per smem stage (2880/120 = 24 chunks)
#define HPAD 124        // pad: stride 124 words == 28 mod 32 banks -> conflict-free strided access
#define NTHREADS 128

// Packed dual-fp32 FMA (only reachable via PTX fma.rn.f32x2; ptxas never auto-fuses)
__device__ __forceinline__ void fma2(unsigned long long &acc,
                                     unsigned long long a,
                                     unsigned long long b) {
    asm("fma.rn.f32x2 %0, %1, %2, %3;" : "=l"(acc) : "l"(a), "l"(b), "l"(acc));
}

__global__ __launch_bounds__(NTHREADS) void gate_kernel(
    const float* __restrict__ X,     // [T, H]
    const float* __restrict__ W,     // [E, H]
    const float* __restrict__ bias,  // [E]
    float* __restrict__ out,         // [T*K] idx-as-float, then [T*K] weights
    int T)
{
    __shared__ float xs[TOK_TILE][HPAD];
    __shared__ float ws[NEXP][HPAD];

    const int tid = threadIdx.x;
    const int t0  = blockIdx.x * TOK_TILE;
    const int et  = tid & 7;    // expert-thread 0..7  (owns experts et + 8*j)
    const int tt  = tid >> 3;   // token-thread  0..15 (owns tokens  tt + 16*i)

    // 4 tokens x 4 experts per thread, accumulated as packed {even-h, odd-h} sums
    unsigned long long acc[4][4];
    #pragma unroll
    for (int i = 0; i < 4; i++)
        #pragma unroll
        for (int j = 0; j < 4; j++) acc[i][j] = 0ULL;

    for (int h0 = 0; h0 < HDIM; h0 += HC) {
        // ---- stage X tile [64 x HC] into smem (float4, coalesced) ----
        #pragma unroll 4
        for (int idx = tid; idx < TOK_TILE * (HC / 4); idx += NTHREADS) {
            int row = idx / (HC / 4);
            int col = (idx % (HC / 4)) * 4;
            *(float4*)&xs[row][col] =
                *(const float4*)&X[(size_t)(t0 + row) * HDIM + h0 + col];
        }
        // ---- stage W tile [32 x HC] ----
        #pragma unroll 2
        for (int idx = tid; idx < NEXP * (HC / 4); idx += NTHREADS) {
            int row = idx / (HC / 4);
            int col = (idx % (HC / 4)) * 4;
            *(float4*)&ws[row][col] =
                *(const float4*)&W[(size_t)row * HDIM + h0 + col];
        }
        __syncthreads();

        // ---- compute: 30 h-steps of 4 columns each ----
        #pragma unroll 6
        for (int h = 0; h < HC; h += 4) {
            ulonglong2 xv[4], wv[4];
            #pragma unroll
            for (int i = 0; i < 4; i++)
                xv[i] = *(const ulonglong2*)&xs[tt + 16 * i][h];
            #pragma unroll
            for (int j = 0; j < 4; j++)
                wv[j] = *(const ulonglong2*)&ws[et + 8 * j][h];
            #pragma unroll
            for (int i = 0; i < 4; i++)
                #pragma unroll
                for (int j = 0; j < 4; j++) {
                    fma2(acc[i][j], xv[i].x, wv[j].x);
                    fma2(acc[i][j], xv[i].y, wv[j].y);
                }
        }
        __syncthreads();
    }

    // ---- reduce packed halves, park logits in smem (reuse xs; padded stride 33) ----
    float* logits = &xs[0][0];  // [64][33] overlay, 8448 floats << xs size
    #pragma unroll
    for (int i = 0; i < 4; i++) {
        int tok = tt + 16 * i;
        #pragma unroll
        for (int j = 0; j < 4; j++) {
            int e = et + 8 * j;
            float lo = __uint_as_float((unsigned)(acc[i][j] & 0xffffffffULL));
            float hi = __uint_as_float((unsigned)(acc[i][j] >> 32));
            logits[tok * 33 + e] = lo + hi;
        }
    }
    __syncthreads();

    // ---- per-token top-4 (strict > scanning ascending e == jax tie-break) + softmax ----
    if (tid < TOK_TILE) {
        const int t = tid;
        float b0 = -3.4e38f, b1 = -3.4e38f, b2 = -3.4e38f, b3 = -3.4e38f;
        int   i0 = 0, i1 = 0, i2 = 0, i3 = 0;
        #pragma unroll
        for (int e = 0; e < NEXP; e++) {
            float v = logits[t * 33 + e] + bias[e];
            if (v > b3) {
                if (v > b0)      { b3=b2;i3=i2; b2=b1;i2=i1; b1=b0;i1=i0; b0=v;i0=e; }
                else if (v > b1) { b3=b2;i3=i2; b2=b1;i2=i1; b1=v;i1=e; }
                else if (v > b2) { b3=b2;i3=i2; b2=v;i2=e; }
                else             { b3=v;i3=e; }
            }
        }
        float e0 = __expf(b0 - b0);
        float e1 = __expf(b1 - b0);
        float e2 = __expf(b2 - b0);
        float e3 = __expf(b3 - b0);
        float inv = 1.0f / (e0 + e1 + e2 + e3);

        size_t base = (size_t)(t0 + t) * TOPK;
        out[base + 0] = (float)i0;
        out[base + 1] = (float)i1;
        out[base + 2] = (float)i2;
        out[base + 3] = (float)i3;
        float* outw = out + (size_t)T * TOPK;
        outw[base + 0] = e0 * inv;
        outw[base + 1] = e1 * inv;
        outw[base + 2] = e2 * inv;
        outw[base + 3] = e3 * inv;
    }
}

extern "C" void kernel_launch(void* const* d_in, const int* in_sizes, int n_in,
                              void* d_out, int out_size) {
    const float* X    = (const float*)d_in[0];
    const float* W    = (const float*)d_in[1];
    const float* bias = (const float*)d_in[2];
    int T = in_sizes[0] / HDIM;          // 16384
    int blocks = T / TOK_TILE;           // 256
    gate_kernel<<<blocks, NTHREADS>>>(X, W, bias, (float*)d_out, T);
}

// round 3
// speedup vs baseline: 1.1070x; 1.1070x over previous
#include <cuda_runtime.h>

#define HDIM 2880
#define NEXP 32
#define TOPK 4
#define TOK_TILE 32
#define HC 80           // H-chunk per stage (2880/80 = 36 chunks)
#define HPAD 84         // 84 mod 32 = 20 -> rows 0..7 hit banks {0,20,8,28,16,4,24,12}: conflict-free
#define NCHUNK (HDIM / HC)
#define NTHREADS 128
#define F4_PER_ROW (HC / 4)                 // 20
#define F4_PER_TILE (TOK_TILE * F4_PER_ROW) // 640
#define F4_PER_THREAD (F4_PER_TILE / NTHREADS) // 5

// Packed dual-fp32 FMA (PTX-only; ptxas never auto-fuses to FFMA2)
__device__ __forceinline__ void fma2(unsigned long long &acc,
                                     unsigned long long a,
                                     unsigned long long b) {
    asm("fma.rn.f32x2 %0, %1, %2, %3;" : "=l"(acc) : "l"(a), "l"(b), "l"(acc));
}

__device__ __forceinline__ void cp_async16(unsigned saddr, const void* gaddr) {
    asm volatile("cp.async.cg.shared.global [%0], [%1], 16;" :: "r"(saddr), "l"(gaddr));
}

__global__ __launch_bounds__(NTHREADS) void gate_kernel(
    const float* __restrict__ X,     // [T, H]
    const float* __restrict__ W,     // [E, H]
    const float* __restrict__ bias,  // [E]
    float* __restrict__ out,         // [T*K] idx-as-float, then [T*K] weights
    int T)
{
    __shared__ float xs[2][TOK_TILE][HPAD];
    __shared__ float ws[2][NEXP][HPAD];

    const int tid = threadIdx.x;
    const int t0  = blockIdx.x * TOK_TILE;
    const int et  = tid & 7;    // expert-thread 0..7  (experts et + 8*j)
    const int tt  = tid >> 3;   // token-thread  0..15 (tokens  tt, tt+16)

    // ---- per-thread async-load addressing (precomputed) ----
    // idx = tid + it*128 over [0,640): row = idx/20, col4 = idx%20
    unsigned xrow[F4_PER_THREAD], xcol[F4_PER_THREAD];
    #pragma unroll
    for (int it = 0; it < F4_PER_THREAD; it++) {
        int idx = tid + it * NTHREADS;
        xrow[it] = idx / F4_PER_ROW;
        xcol[it] = (idx % F4_PER_ROW) * 4;
    }

    // 2 tokens x 4 experts per thread, packed {even-h, odd-h} accumulators
    unsigned long long acc[2][4];
    #pragma unroll
    for (int i = 0; i < 2; i++)
        #pragma unroll
        for (int j = 0; j < 4; j++) acc[i][j] = 0ULL;

    // ---- issue loads for chunk c into stage b ----
    auto load_chunk = [&](int c, int b) {
        const float* Xc = X + (size_t)t0 * HDIM + c * HC;
        const float* Wc = W + c * HC;
        #pragma unroll
        for (int it = 0; it < F4_PER_THREAD; it++) {
            unsigned s = (unsigned)__cvta_generic_to_shared(&ws[b][xrow[it]][xcol[it]]);
            cp_async16(s, Wc + (size_t)xrow[it] * HDIM + xcol[it]);
        }
        #pragma unroll
        for (int it = 0; it < F4_PER_THREAD; it++) {
            unsigned s = (unsigned)__cvta_generic_to_shared(&xs[b][xrow[it]][xcol[it]]);
            cp_async16(s, Xc + (size_t)xrow[it] * HDIM + xcol[it]);
        }
        asm volatile("cp.async.commit_group;");
    };

    load_chunk(0, 0);

    for (int c = 0; c < NCHUNK; c++) {
        const int b = c & 1;
        if (c + 1 < NCHUNK) {
            load_chunk(c + 1, b ^ 1);                    // prefetch next stage
            asm volatile("cp.async.wait_group 1;");      // chunk c is complete
        } else {
            asm volatile("cp.async.wait_group 0;");
        }
        __syncthreads();

        const float* xr0 = xs[b][tt];
        const float* xr1 = xs[b][tt + 16];
        const float* wr0 = ws[b][et];
        const float* wr1 = ws[b][et + 8];
        const float* wr2 = ws[b][et + 16];
        const float* wr3 = ws[b][et + 24];

        #pragma unroll 5
        for (int h = 0; h < HC; h += 4) {
            ulonglong2 x0 = *(const ulonglong2*)(xr0 + h);
            ulonglong2 x1 = *(const ulonglong2*)(xr1 + h);
            ulonglong2 w0 = *(const ulonglong2*)(wr0 + h);
            ulonglong2 w1 = *(const ulonglong2*)(wr1 + h);
            ulonglong2 w2 = *(const ulonglong2*)(wr2 + h);
            ulonglong2 w3 = *(const ulonglong2*)(wr3 + h);
            fma2(acc[0][0], x0.x, w0.x); fma2(acc[0][0], x0.y, w0.y);
            fma2(acc[0][1], x0.x, w1.x); fma2(acc[0][1], x0.y, w1.y);
            fma2(acc[0][2], x0.x, w2.x); fma2(acc[0][2], x0.y, w2.y);
            fma2(acc[0][3], x0.x, w3.x); fma2(acc[0][3], x0.y, w3.y);
            fma2(acc[1][0], x1.x, w0.x); fma2(acc[1][0], x1.y, w0.y);
            fma2(acc[1][1], x1.x, w1.x); fma2(acc[1][1], x1.y, w1.y);
            fma2(acc[1][2], x1.x, w2.x); fma2(acc[1][2], x1.y, w2.y);
            fma2(acc[1][3], x1.x, w3.x); fma2(acc[1][3], x1.y, w3.y);
        }
        __syncthreads();
    }

    // ---- reduce packed halves, park logits in smem (reuse xs; stride 33) ----
    float* logits = &xs[0][0][0];  // [32][33] overlay = 1056 floats
    #pragma unroll
    for (int i = 0; i < 2; i++) {
        int tok = tt + 16 * i;
        #pragma unroll
        for (int j = 0; j < 4; j++) {
            int e = et + 8 * j;
            float lo = __uint_as_float((unsigned)(acc[i][j] & 0xffffffffULL));
            float hi = __uint_as_float((unsigned)(acc[i][j] >> 32));
            logits[tok * 33 + e] = lo + hi;
        }
    }
    __syncthreads();

    // ---- per-token top-4 (strict >, ascending e == jax tie-break) + softmax ----
    if (tid < TOK_TILE) {
        const int t = tid;
        float b0 = -3.4e38f, b1 = -3.4e38f, b2 = -3.4e38f, b3 = -3.4e38f;
        int   i0 = 0, i1 = 0, i2 = 0, i3 = 0;
        #pragma unroll
        for (int e = 0; e < NEXP; e++) {
            float v = logits[t * 33 + e] + bias[e];
            if (v > b3) {
                if (v > b0)      { b3=b2;i3=i2; b2=b1;i2=i1; b1=b0;i1=i0; b0=v;i0=e; }
                else if (v > b1) { b3=b2;i3=i2; b2=b1;i2=i1; b1=v;i1=e; }
                else if (v > b2) { b3=b2;i3=i2; b2=v;i2=e; }
                else             { b3=v;i3=e; }
            }
        }
        float e0 = __expf(b0 - b0);
        float e1 = __expf(b1 - b0);
        float e2 = __expf(b2 - b0);
        float e3 = __expf(b3 - b0);
        float inv = 1.0f / (e0 + e1 + e2 + e3);

        size_t base = (size_t)(t0 + t) * TOPK;
        out[base + 0] = (float)i0;
        out[base + 1] = (float)i1;
        out[base + 2] = (float)i2;
        out[base + 3] = (float)i3;
        float* outw = out + (size_t)T * TOPK;
        outw[base + 0] = e0 * inv;
        outw[base + 1] = e1 * inv;
        outw[base + 2] = e2 * inv;
        outw[base + 3] = e3 * inv;
    }
}

extern "C" void kernel_launch(void* const* d_in, const int* in_sizes, int n_in,
                              void* d_out, int out_size) {
    const float* X    = (const float*)d_in[0];
    const float* W    = (const float*)d_in[1];
    const float* bias = (const float*)d_in[2];
    int T = in_sizes[0] / HDIM;          // 16384
    int blocks = T / TOK_TILE;           // 512
    gate_kernel<<<blocks, NTHREADS>>>(X, W, bias, (float*)d_out, T);
}